// round 1
// baseline (speedup 1.0000x reference)
#include <cuda_runtime.h>
#include <cuda_bf16.h>

#define EPS 0.01f

// scalar accumulator in device global memory (no allocation allowed)
__device__ float g_acc;

__global__ void elc_zero_kernel() { g_acc = 0.0f; }

__global__ void __launch_bounds__(256)
elc_main_kernel(const float4* __restrict__ pred4,
                const int4*   __restrict__ label4,
                const float*  __restrict__ Wl,
                const float4* __restrict__ em4,
                int n4, int n_total)
{
    __shared__ float sWl[16];
    if (threadIdx.x < 16) sWl[threadIdx.x] = Wl[threadIdx.x];
    __syncthreads();

    float acc = 0.0f;
    const int stride = gridDim.x * blockDim.x;
    for (int i = blockIdx.x * blockDim.x + threadIdx.x; i < n4; i += stride) {
        float4 p = pred4[i];
        int4   l = label4[i];
        float4 e = em4[i];
        // element index = 4*i ; c = (4*i >> 18) & 15  (H*W = 2^18, C = 16)
        const float w = sWl[(i >> 16) & 15];

        float t = 0.0f;
        if (l.x == 1) t += __logf(p.x + EPS) * e.x;
        if (l.y == 1) t += __logf(p.y + EPS) * e.y;
        if (l.z == 1) t += __logf(p.z + EPS) * e.z;
        if (l.w == 1) t += __logf(p.w + EPS) * e.w;
        acc = fmaf(-w, t, acc);
    }

    // scalar tail (defensive; n_total is divisible by 4 for this problem)
    if (blockIdx.x == 0 && threadIdx.x == 0) {
        const float* pred  = (const float*)pred4;
        const int*   label = (const int*)label4;
        const float* em    = (const float*)em4;
        for (int e = n4 * 4; e < n_total; ++e) {
            if (label[e] == 1) {
                const float w = sWl[(e >> 18) & 15];
                acc -= w * __logf(pred[e] + EPS) * em[e];
            }
        }
    }

    // warp reduce
    #pragma unroll
    for (int o = 16; o > 0; o >>= 1)
        acc += __shfl_xor_sync(0xffffffff, acc, o);

    __shared__ float red[8];
    const int lane = threadIdx.x & 31;
    const int wid  = threadIdx.x >> 5;
    if (lane == 0) red[wid] = acc;
    __syncthreads();
    if (wid == 0) {
        acc = (lane < (blockDim.x >> 5)) ? red[lane] : 0.0f;
        #pragma unroll
        for (int o = 4; o > 0; o >>= 1)
            acc += __shfl_xor_sync(0xffffffff, acc, o);
        if (lane == 0) atomicAdd(&g_acc, acc);
    }
}

__global__ void elc_finalize_kernel(const float* __restrict__ label_sum,
                                    int n_ls, float* __restrict__ out)
{
    float s = 0.0f;
    for (int i = 0; i < n_ls; ++i) s += label_sum[i];
    out[0] = g_acc / s;
}

extern "C" void kernel_launch(void* const* d_in, const int* in_sizes, int n_in,
                              void* d_out, int out_size)
{
    // metadata order: pred(f32), label(i32), Wl(f32[16]), label_sum(f32[16]), existmap(f32)
    const float* pred      = (const float*)d_in[0];
    const int*   label     = (const int*)  d_in[1];
    const float* Wl        = (const float*)d_in[2];
    const float* label_sum = (const float*)d_in[3];
    const float* em        = (const float*)d_in[4];
    float* out = (float*)d_out;

    const int n_total = in_sizes[0];
    const int n4 = n_total >> 2;

    elc_zero_kernel<<<1, 1>>>();

    const int threads = 256;
    int blocks = 1184;  // 8 CTAs/SM * 148 SMs
    int max_blocks = (n4 + threads - 1) / threads;
    if (blocks > max_blocks) blocks = max_blocks;
    if (blocks < 1) blocks = 1;

    elc_main_kernel<<<blocks, threads>>>(
        (const float4*)pred, (const int4*)label, Wl, (const float4*)em,
        n4, n_total);

    elc_finalize_kernel<<<1, 1>>>(label_sum, in_sizes[3], out);
}